// round 14
// baseline (speedup 1.0000x reference)
#include <cuda_runtime.h>
#include <cuda_bf16.h>

// ---------------- problem constants / scratch capacities ----------------
#define MAXB 8
#define MAXN 200000
#define KPRE 512
#define GCAP 2048
#define MAXDET 300
#define NBIN 65536
#define SCORE_THR 0.05f
#define IOU_THR 0.5f
// fine radix bins: bin = (key - KEY_BASE) >> 7, covering [0.5, 1.0) in 128-ULP steps
#define KEY_BASE 0x3F000000u

// ---------------- device scratch (static zero-init; kernels restore zeros) ----------------
__device__ float               d_score[MAXB * MAXN];
__device__ int                 d_label[MAXB * MAXN];
__device__ unsigned int        d_hist[MAXB * NBIN];   // fine histogram; zeroed by gatherK after use
__device__ unsigned int        d_T[MAXB];
__device__ unsigned long long  d_gath[MAXB * GCAP];   // only first d_cnt[b] entries read
__device__ int                 d_cnt[MAXB];           // reset by finalizeK after use

// ---------------- fine-bin helper ----------------
__device__ __forceinline__ int fine_bin(unsigned key) {
    if (key < KEY_BASE) return 0;
    unsigned d = key - KEY_BASE;
    return (d >= (NBIN << 7)) ? (NBIN - 1) : (int)(d >> 7);
}

// ---------------- K1 (fast, C==80): 4 threads/row, coalesced (proven) ----------------
__global__ void scoreK80(const float* __restrict__ cls, int N) {
    int t   = blockIdx.x * blockDim.x + threadIdx.x;
    int row = t >> 2;
    int sub = t & 3;
    int b   = blockIdx.y;
    bool valid = row < N;
    int rclamp = valid ? row : (N - 1);
    const float4* r4 = (const float4*)(cls + ((size_t)b * N + rclamp) * 80);

    float best = -1e30f; int bi = 0;
    #pragma unroll
    for (int k = 0; k < 5; k++) {
        float4 v = r4[sub + 4 * k];
        int e = (sub + 4 * k) * 4;
        if (v.x > best) { best = v.x; bi = e;     }
        if (v.y > best) { best = v.y; bi = e + 1; }
        if (v.z > best) { best = v.z; bi = e + 2; }
        if (v.w > best) { best = v.w; bi = e + 3; }
    }
    #pragma unroll
    for (int off = 2; off >= 1; off >>= 1) {
        float ov = __shfl_down_sync(0xFFFFFFFFu, best, off);
        int   oi = __shfl_down_sync(0xFFFFFFFFu, bi,   off);
        if (ov > best || (ov == best && oi < bi)) { best = ov; bi = oi; }
    }
    if (sub == 0 && valid) {
        size_t base = (size_t)b * N + row;
        d_score[base] = best;
        d_label[base] = bi;
        if (best > SCORE_THR) {
            int bin = fine_bin(__float_as_uint(best));
            atomicAdd(&d_hist[(b << 16) + bin], 1u);
        }
    }
}

// ---------------- K1 (generic fallback) ----------------
__global__ void scoreKgen(const float* __restrict__ cls, int N, int C) {
    int b = blockIdx.y;
    int n = blockIdx.x * blockDim.x + threadIdx.x;
    if (n >= N) return;
    size_t base = (size_t)b * N + n;
    const float* row = cls + base * C;
    float best = row[0]; int bi = 0;
    for (int k = 1; k < C; k++) { float v = row[k]; if (v > best) { best = v; bi = k; } }
    d_score[base] = best;
    d_label[base] = bi;
    if (best > SCORE_THR) {
        int bin = fine_bin(__float_as_uint(best));
        atomicAdd(&d_hist[(b << 16) + bin], 1u);
    }
}

// ---------------- K2: single-level fine-bin selection (warp-shuffle suffix scans) ----------------
__global__ __launch_bounds__(1024, 1) void selectTK() {
    __shared__ unsigned cs[256];
    __shared__ unsigned bs[256];
    __shared__ unsigned warpTot[8];
    __shared__ int s_chunk, s_bin;
    __shared__ unsigned s_above1;

    int b   = blockIdx.x;
    int tid = threadIdx.x;
    int w   = tid >> 5, l = tid & 31;
    const unsigned* H = d_hist + b * NBIN;
    const int target = KPRE;

    if (tid == 0) { s_chunk = -1; s_bin = 0; s_above1 = 0; }

    // chunk sums (vectorized): warp w covers chunks [8w, 8w+8)
    #pragma unroll
    for (int cc = 0; cc < 8; cc++) {
        int c = w * 8 + cc;
        const uint4* p = (const uint4*)(H + c * 256);
        uint4 v0 = p[l];
        uint4 v1 = p[l + 32];
        unsigned s = v0.x + v0.y + v0.z + v0.w + v1.x + v1.y + v1.z + v1.w;
        #pragma unroll
        for (int off = 16; off >= 1; off >>= 1)
            s += __shfl_down_sync(0xFFFFFFFFu, s, off);
        if (l == 0) cs[c] = s;
    }
    __syncthreads();

    // --- suffix scan over 256 chunk sums: warp-shuffle + warp-total combine ---
    unsigned v1s = 0;
    if (tid < 256) {
        v1s = cs[tid];
        #pragma unroll
        for (int off = 1; off < 32; off <<= 1) {
            unsigned o = __shfl_down_sync(0xFFFFFFFFu, v1s, off);
            if (l + off < 32) v1s += o;
        }
        if (l == 0) warpTot[w] = v1s;           // warp suffix total (value at lane 0)
    }
    __syncthreads();
    if (tid < 256) {
        unsigned add = 0;
        #pragma unroll
        for (int u = 0; u < 8; u++) if (u > w) add += warpTot[u];
        cs[tid] = v1s + add;
    }
    __syncthreads();
    if (tid < 256) {
        unsigned sfx = cs[tid];
        unsigned nxt = (tid == 255) ? 0u : cs[tid + 1];
        if (sfx >= (unsigned)target && nxt < (unsigned)target) { s_chunk = tid; s_above1 = nxt; }
    }
    __syncthreads();

    int c = s_chunk;
    if (c < 0) {                 // fewer than 512 valid -> gather everything above thr
        if (tid == 0) d_T[b] = 1u;
        return;
    }
    int target2 = target - (int)s_above1;

    // --- suffix scan over the 256 bins of chunk c (same technique) ---
    unsigned v2s = 0;
    if (tid < 256) {
        v2s = H[c * 256 + tid];
        #pragma unroll
        for (int off = 1; off < 32; off <<= 1) {
            unsigned o = __shfl_down_sync(0xFFFFFFFFu, v2s, off);
            if (l + off < 32) v2s += o;
        }
        if (l == 0) warpTot[w] = v2s;
    }
    __syncthreads();
    if (tid < 256) {
        unsigned add = 0;
        #pragma unroll
        for (int u = 0; u < 8; u++) if (u > w) add += warpTot[u];
        bs[tid] = v2s + add;
    }
    __syncthreads();
    if (tid < 256) {
        unsigned sfx = bs[tid];
        unsigned nxt = (tid == 255) ? 0u : bs[tid + 1];
        if (sfx >= (unsigned)target2 && nxt < (unsigned)target2) s_bin = tid;
    }
    __syncthreads();

    if (tid == 0) {
        int bin = c * 256 + s_bin;
        d_T[b] = (bin == 0) ? 1u : (KEY_BASE + ((unsigned)bin << 7));
    }
}

// ---------------- K3: gather candidates with key >= T; also zero d_hist for next replay ----------
__global__ void gatherK(int N, int gx) {
    int b  = blockIdx.y;
    int q  = blockIdx.x * blockDim.x + threadIdx.x;
    int n0 = q * 4;

    {
        int flat = (b * gx + blockIdx.x) * blockDim.x + threadIdx.x;
        int total = gx * MAXB * blockDim.x;
        for (int i = flat; i < MAXB * NBIN; i += total) d_hist[i] = 0u;
    }

    if (n0 >= N) return;
    unsigned T = d_T[b];
    const float* S = d_score + (size_t)b * N;
    if (n0 + 3 < N) {
        float4 v = *(const float4*)(S + n0);
        float vv[4] = {v.x, v.y, v.z, v.w};
        #pragma unroll
        for (int k = 0; k < 4; k++) {
            if (vv[k] > SCORE_THR) {
                unsigned key = __float_as_uint(vv[k]);
                if (key >= T) {
                    int p = atomicAdd(&d_cnt[b], 1);
                    if (p < GCAP)
                        d_gath[b * GCAP + p] =
                            ((unsigned long long)key << 32) | (unsigned)(~(unsigned)(n0 + k));
                }
            }
        }
    } else {
        for (int k = 0; k < 4 && n0 + k < N; k++) {
            float s = S[n0 + k];
            if (s > SCORE_THR) {
                unsigned key = __float_as_uint(s);
                if (key >= T) {
                    int p = atomicAdd(&d_cnt[b], 1);
                    if (p < GCAP)
                        d_gath[b * GCAP + p] =
                            ((unsigned long long)key << 32) | (unsigned)(~(unsigned)(n0 + k));
                }
            }
        }
    }
}

// ---------------- K4: rank-sort, decode+clip, balanced mask, Jacobi NMS, output ----------------
__global__ __launch_bounds__(1024, 1) void finalizeK(
    const float* __restrict__ anchors, const float* __restrict__ regs,
    const float* __restrict__ sizes, float* __restrict__ out, int N, int B)
{
    int b = blockIdx.x;
    int tid = threadIdx.x;

    __shared__ __align__(16) unsigned char sm[47296];
    __shared__ int s_changed;
    unsigned int*       maskT = (unsigned int*)sm;            // [512][16] (after decode)
    unsigned long long* arr   = (unsigned long long*)sm;      // [2048] raw gathered (sort phase)
    unsigned long long* arrS  = (unsigned long long*)(sm + 16384); // [512] top-512 sorted
    int*                ranks = (int*)(sm + 20480);           // [2048] partial ranks (sort phase)
    float4*             sBox  = (float4*)(sm + 32768);
    float*              sArea = (float*) (sm + 40960);
    float*              sScore= (float*) (sm + 43008);
    int*                sLabel= (int*)   (sm + 45056);
    unsigned int*       keepW = (unsigned int*)(sm + 47104);
    int*                warpCnt = (int*)(sm + 47168);

    int cnt = d_cnt[b]; if (cnt > GCAP) cnt = GCAP;
    int nv  = cnt < KPRE ? cnt : KPRE;

    for (int i = tid; i < cnt; i += blockDim.x) {
        arr[i] = d_gath[b * GCAP + i];
        ranks[i] = 0;
    }
    __syncthreads();
    if (tid == 0) d_cnt[b] = 0;     // reset for next graph replay (after read)

    // ---- rank computation: 2 half-scan tasks per element spread over ALL 1024 threads ----
    {
        int mid = cnt >> 1;
        int ntask = cnt * 2;
        for (int tt = tid; tt < ntask; tt += blockDim.x) {
            int e = tt >> 1;
            int h = tt & 1;
            int j0 = h ? mid : 0;
            int j1 = h ? cnt : mid;
            unsigned long long mine = arr[e];
            int r = 0;
            int j = j0;
            for (; j + 4 <= j1; j += 4) {
                r += (arr[j]     > mine);
                r += (arr[j + 1] > mine);
                r += (arr[j + 2] > mine);
                r += (arr[j + 3] > mine);
            }
            for (; j < j1; j++) r += (arr[j] > mine);
            if (r) atomicAdd(&ranks[e], r);
        }
    }
    __syncthreads();
    for (int e = tid; e < cnt; e += blockDim.x) {
        int r = ranks[e];
        if (r < KPRE) arrS[r] = arr[e];
    }
    __syncthreads();

    // decode + clip boxes for top nv; default-fill output with -1
    float H = sizes[b * 2 + 0], W = sizes[b * 2 + 1];
    if (tid < nv) {
        unsigned long long v = arrS[tid];
        unsigned key = (unsigned)(v >> 32);
        int idx = (int)(~(unsigned)v);
        size_t off = (size_t)b * N + idx;
        float4 a = ((const float4*)anchors)[off];
        float4 r = ((const float4*)regs)[off];
        float w = a.z - a.x, h = a.w - a.y;
        float cx = a.x + 0.5f * w, cy = a.y + 0.5f * h;
        float dx = r.x * 0.1f, dy = r.y * 0.1f, dw = r.z * 0.2f, dh = r.w * 0.2f;
        float pcx = cx + dx * w, pcy = cy + dy * h;
        float pw = expf(dw) * w, ph = expf(dh) * h;
        float x1 = pcx - 0.5f * pw, y1 = pcy - 0.5f * ph;
        float x2 = pcx + 0.5f * pw, y2 = pcy + 0.5f * ph;
        x1 = fminf(fmaxf(x1, 0.f), W); x2 = fminf(fmaxf(x2, 0.f), W);
        y1 = fminf(fmaxf(y1, 0.f), H); y2 = fminf(fmaxf(y2, 0.f), H);
        sBox[tid]  = make_float4(x1, y1, x2, y2);
        sArea[tid] = (x2 - x1) * (y2 - y1);
        sScore[tid]= __uint_as_float(key);
        sLabel[tid]= d_label[off];
    }
    float* outB = out;
    float* outS = out + (size_t)B * MAXDET * 4;
    float* outL = out + (size_t)B * MAXDET * 5;
    if (tid < MAXDET) {
        ((float4*)outB)[b * MAXDET + tid] = make_float4(-1.f, -1.f, -1.f, -1.f);
        outS[b * MAXDET + tid] = -1.f;
        outL[b * MAXDET + tid] = -1.f;
    }
    __syncthreads();   // arrS/ranks reads done -> maskT may now overwrite that region

    // ---- zero maskT (tasks below only write in-range words) ----
    {
        uint4* mz = (uint4*)maskT;      // 2048 uint4
        mz[tid] = make_uint4(0u, 0u, 0u, 0u);
        mz[tid + 1024] = make_uint4(0u, 0u, 0u, 0u);
    }
    __syncthreads();

    // ---- balanced TRANSPOSED mask build: row pairs (p, 511-p), 4 threads/pair ----
    // Combined word count per pair is ~16 (constant) -> each thread <=5 word-tasks (~160 IoUs max).
    {
        int p = tid & 255;
        int h = tid >> 8;               // 0..3
        int rowA = p, rowB = 511 - p;
        int wa = (rowA + 31) >> 5;      // words needed for row A (j < rowA)
        int wb = (rowB + 31) >> 5;
        int L = wa + wb;
        for (int q = h; q < L; q += 4) {
            int row, w;
            if (q < wa) { row = rowA; w = q; }
            else        { row = rowB; w = q - wa; }
            if (row >= nv) continue;    // invalid rows: leave zero
            float4 bi = sBox[row];
            float  ai = sArea[row];
            int j0 = w * 32;
            int j1 = j0 + 32;
            int jmax = row < nv ? row : nv;
            if (j1 > jmax) j1 = jmax;
            unsigned word = 0;
            for (int j = j0; j < j1; j++) {
                float4 bj = sBox[j];
                float lx = fmaxf(bi.x, bj.x), ly = fmaxf(bi.y, bj.y);
                float rx = fminf(bi.z, bj.z), ry = fminf(bi.w, bj.w);
                float iw = fmaxf(rx - lx, 0.f), ih = fmaxf(ry - ly, 0.f);
                float inter = iw * ih;
                float lhs = inter * (1.0f + IOU_THR);
                float rhs = IOU_THR * (ai + sArea[j] + 1e-9f);
                if (lhs > rhs) word |= 1u << (j & 31);
            }
            if (word) maskT[row * 16 + w] = word;
        }
    }
    // init keep = all valid
    if (tid < 16) {
        int full = nv >> 5, rem = nv & 31;
        keepW[tid] = (tid < full) ? 0xFFFFFFFFu
                   : ((tid == full && rem) ? ((1u << rem) - 1u) : 0u);
    }
    __syncthreads();

    // ---- Jacobi fixpoint iteration: keep[i] = valid[i] && !(exists j<i kept with iou>thr) ----
    for (int it = 0; it < KPRE + 8; it++) {
        unsigned sup = 0;
        if (tid < 512) {
            const uint4* mrow = (const uint4*)(maskT + tid * 16);
            uint4 m0 = mrow[0], m1 = mrow[1], m2 = mrow[2], m3 = mrow[3];
            sup |= (m0.x & keepW[0])  | (m0.y & keepW[1])  | (m0.z & keepW[2])  | (m0.w & keepW[3]);
            sup |= (m1.x & keepW[4])  | (m1.y & keepW[5])  | (m1.z & keepW[6])  | (m1.w & keepW[7]);
            sup |= (m2.x & keepW[8])  | (m2.y & keepW[9])  | (m2.z & keepW[10]) | (m2.w & keepW[11]);
            sup |= (m3.x & keepW[12]) | (m3.y & keepW[13]) | (m3.z & keepW[14]) | (m3.w & keepW[15]);
        }
        bool nb = (tid < nv) && (sup == 0u);
        if (tid == 0) s_changed = 0;
        __syncthreads();
        unsigned wm = __ballot_sync(0xFFFFFFFFu, nb);
        if (tid < 512 && (tid & 31) == 0) {
            int w = tid >> 5;
            if (wm != keepW[w]) { keepW[w] = wm; s_changed = 1; }
        }
        __syncthreads();
        if (!s_changed) break;
    }

    // compact kept candidates (score order) into first <=300 slots
    bool kept = false;
    if (tid < nv) kept = (keepW[tid >> 5] >> (tid & 31)) & 1u;
    unsigned wm = __ballot_sync(0xFFFFFFFFu, kept);
    int w = tid >> 5, lane = tid & 31;
    if (lane == 0) warpCnt[w] = __popc(wm);
    __syncthreads();
    if (kept) {
        int prefix = 0;
        for (int i = 0; i < w; i++) prefix += warpCnt[i];
        int pos = prefix + __popc(wm & ((1u << lane) - 1u));
        if (pos < MAXDET) {
            ((float4*)outB)[b * MAXDET + pos] = sBox[tid];
            outS[b * MAXDET + pos] = sScore[tid];
            outL[b * MAXDET + pos] = (float)sLabel[tid];
        }
    }
}

// ---------------- launch ----------------
extern "C" void kernel_launch(void* const* d_in, const int* in_sizes, int n_in,
                              void* d_out, int out_size) {
    const float* anchors = (const float*)d_in[0];
    const float* regs    = (const float*)d_in[1];
    const float* cls     = (const float*)d_in[2];
    const float* sizes   = (const float*)d_in[3];

    int B = in_sizes[3] / 2;            // sizes is [B,2]
    if (B <= 0 || B > MAXB) B = MAXB;
    int N = in_sizes[0] / (B * 4);      // anchors [B,N,4]
    long long clsElems = (long long)in_sizes[2];
    int C = (int)(clsElems / ((long long)B * N));

    int N4 = (N + 3) / 4;
    int gx = (N4 + 255) / 256;
    dim3 gridV(gx, B);

    if (C == 80) {
        dim3 gridS(((N * 4) + 255) / 256, B);
        scoreK80<<<gridS, 256>>>(cls, N);
    } else {
        dim3 gridBN((N + 255) / 256, B);
        scoreKgen<<<gridBN, 256>>>(cls, N, C);
    }
    selectTK<<<B, 1024>>>();
    gatherK<<<gridV, 256>>>(N, gx);
    finalizeK<<<B, 1024>>>(anchors, regs, sizes, (float*)d_out, N, B);
}

// round 15
// speedup vs baseline: 1.0315x; 1.0315x over previous
#include <cuda_runtime.h>
#include <cuda_bf16.h>

// ---------------- problem constants / scratch capacities ----------------
#define MAXB 8
#define MAXN 200000
#define KPRE 512
#define GCAP 2048
#define MAXDET 300
#define NBIN 65536
#define SCORE_THR 0.05f
#define IOU_THR 0.5f
// fine radix bins: bin = (key - KEY_BASE) >> 7, covering [0.5, 1.0) in 128-ULP steps
#define KEY_BASE 0x3F000000u

// ---------------- device scratch (static zero-init; kernels restore zeros) ----------------
__device__ float               d_score[MAXB * MAXN];
__device__ int                 d_label[MAXB * MAXN];
__device__ unsigned int        d_hist[MAXB * NBIN];   // fine histogram; zeroed by gatherK after use
__device__ unsigned int        d_T[MAXB];
__device__ unsigned long long  d_gath[MAXB * GCAP];   // only first d_cnt[b] entries read
__device__ int                 d_cnt[MAXB];           // reset by finalizeK after use
__device__ unsigned long long  d_sort[MAXB * KPRE];   // top-512 sorted keys (written by rankK)

// ---------------- fine-bin helper ----------------
__device__ __forceinline__ int fine_bin(unsigned key) {
    if (key < KEY_BASE) return 0;
    unsigned d = key - KEY_BASE;
    return (d >= (NBIN << 7)) ? (NBIN - 1) : (int)(d >> 7);
}

// ---------------- K1 (fast, C==80): 4 threads/row, coalesced (proven) ----------------
__global__ void scoreK80(const float* __restrict__ cls, int N) {
    int t   = blockIdx.x * blockDim.x + threadIdx.x;
    int row = t >> 2;
    int sub = t & 3;
    int b   = blockIdx.y;
    bool valid = row < N;
    int rclamp = valid ? row : (N - 1);
    const float4* r4 = (const float4*)(cls + ((size_t)b * N + rclamp) * 80);

    float best = -1e30f; int bi = 0;
    #pragma unroll
    for (int k = 0; k < 5; k++) {
        float4 v = r4[sub + 4 * k];
        int e = (sub + 4 * k) * 4;
        if (v.x > best) { best = v.x; bi = e;     }
        if (v.y > best) { best = v.y; bi = e + 1; }
        if (v.z > best) { best = v.z; bi = e + 2; }
        if (v.w > best) { best = v.w; bi = e + 3; }
    }
    #pragma unroll
    for (int off = 2; off >= 1; off >>= 1) {
        float ov = __shfl_down_sync(0xFFFFFFFFu, best, off);
        int   oi = __shfl_down_sync(0xFFFFFFFFu, bi,   off);
        if (ov > best || (ov == best && oi < bi)) { best = ov; bi = oi; }
    }
    if (sub == 0 && valid) {
        size_t base = (size_t)b * N + row;
        d_score[base] = best;
        d_label[base] = bi;
        if (best > SCORE_THR) {
            int bin = fine_bin(__float_as_uint(best));
            atomicAdd(&d_hist[(b << 16) + bin], 1u);
        }
    }
}

// ---------------- K1 (generic fallback) ----------------
__global__ void scoreKgen(const float* __restrict__ cls, int N, int C) {
    int b = blockIdx.y;
    int n = blockIdx.x * blockDim.x + threadIdx.x;
    if (n >= N) return;
    size_t base = (size_t)b * N + n;
    const float* row = cls + base * C;
    float best = row[0]; int bi = 0;
    for (int k = 1; k < C; k++) { float v = row[k]; if (v > best) { best = v; bi = k; } }
    d_score[base] = best;
    d_label[base] = bi;
    if (best > SCORE_THR) {
        int bin = fine_bin(__float_as_uint(best));
        atomicAdd(&d_hist[(b << 16) + bin], 1u);
    }
}

// ---------------- K2: single-level fine-bin selection (warp-shuffle suffix scans) ----------------
__global__ __launch_bounds__(1024, 1) void selectTK() {
    __shared__ unsigned cs[256];
    __shared__ unsigned bs[256];
    __shared__ unsigned warpTot[8];
    __shared__ int s_chunk, s_bin;
    __shared__ unsigned s_above1;

    int b   = blockIdx.x;
    int tid = threadIdx.x;
    int w   = tid >> 5, l = tid & 31;
    const unsigned* H = d_hist + b * NBIN;
    const int target = KPRE;

    if (tid == 0) { s_chunk = -1; s_bin = 0; s_above1 = 0; }

    #pragma unroll
    for (int cc = 0; cc < 8; cc++) {
        int c = w * 8 + cc;
        const uint4* p = (const uint4*)(H + c * 256);
        uint4 v0 = p[l];
        uint4 v1 = p[l + 32];
        unsigned s = v0.x + v0.y + v0.z + v0.w + v1.x + v1.y + v1.z + v1.w;
        #pragma unroll
        for (int off = 16; off >= 1; off >>= 1)
            s += __shfl_down_sync(0xFFFFFFFFu, s, off);
        if (l == 0) cs[c] = s;
    }
    __syncthreads();

    unsigned v1s = 0;
    if (tid < 256) {
        v1s = cs[tid];
        #pragma unroll
        for (int off = 1; off < 32; off <<= 1) {
            unsigned o = __shfl_down_sync(0xFFFFFFFFu, v1s, off);
            if (l + off < 32) v1s += o;
        }
        if (l == 0) warpTot[w] = v1s;
    }
    __syncthreads();
    if (tid < 256) {
        unsigned add = 0;
        #pragma unroll
        for (int u = 0; u < 8; u++) if (u > w) add += warpTot[u];
        cs[tid] = v1s + add;
    }
    __syncthreads();
    if (tid < 256) {
        unsigned sfx = cs[tid];
        unsigned nxt = (tid == 255) ? 0u : cs[tid + 1];
        if (sfx >= (unsigned)target && nxt < (unsigned)target) { s_chunk = tid; s_above1 = nxt; }
    }
    __syncthreads();

    int c = s_chunk;
    if (c < 0) {
        if (tid == 0) d_T[b] = 1u;
        return;
    }
    int target2 = target - (int)s_above1;

    unsigned v2s = 0;
    if (tid < 256) {
        v2s = H[c * 256 + tid];
        #pragma unroll
        for (int off = 1; off < 32; off <<= 1) {
            unsigned o = __shfl_down_sync(0xFFFFFFFFu, v2s, off);
            if (l + off < 32) v2s += o;
        }
        if (l == 0) warpTot[w] = v2s;
    }
    __syncthreads();
    if (tid < 256) {
        unsigned add = 0;
        #pragma unroll
        for (int u = 0; u < 8; u++) if (u > w) add += warpTot[u];
        bs[tid] = v2s + add;
    }
    __syncthreads();
    if (tid < 256) {
        unsigned sfx = bs[tid];
        unsigned nxt = (tid == 255) ? 0u : bs[tid + 1];
        if (sfx >= (unsigned)target2 && nxt < (unsigned)target2) s_bin = tid;
    }
    __syncthreads();

    if (tid == 0) {
        int bin = c * 256 + s_bin;
        d_T[b] = (bin == 0) ? 1u : (KEY_BASE + ((unsigned)bin << 7));
    }
}

// ---------------- K3: gather candidates with key >= T; also zero d_hist for next replay ----------
__global__ void gatherK(int N, int gx) {
    int b  = blockIdx.y;
    int q  = blockIdx.x * blockDim.x + threadIdx.x;
    int n0 = q * 4;

    {
        int flat = (b * gx + blockIdx.x) * blockDim.x + threadIdx.x;
        int total = gx * MAXB * blockDim.x;
        for (int i = flat; i < MAXB * NBIN; i += total) d_hist[i] = 0u;
    }

    if (n0 >= N) return;
    unsigned T = d_T[b];
    const float* S = d_score + (size_t)b * N;
    if (n0 + 3 < N) {
        float4 v = *(const float4*)(S + n0);
        float vv[4] = {v.x, v.y, v.z, v.w};
        #pragma unroll
        for (int k = 0; k < 4; k++) {
            if (vv[k] > SCORE_THR) {
                unsigned key = __float_as_uint(vv[k]);
                if (key >= T) {
                    int p = atomicAdd(&d_cnt[b], 1);
                    if (p < GCAP)
                        d_gath[b * GCAP + p] =
                            ((unsigned long long)key << 32) | (unsigned)(~(unsigned)(n0 + k));
                }
            }
        }
    } else {
        for (int k = 0; k < 4 && n0 + k < N; k++) {
            float s = S[n0 + k];
            if (s > SCORE_THR) {
                unsigned key = __float_as_uint(s);
                if (key >= T) {
                    int p = atomicAdd(&d_cnt[b], 1);
                    if (p < GCAP)
                        d_gath[b * GCAP + p] =
                            ((unsigned long long)key << 32) | (unsigned)(~(unsigned)(n0 + k));
                }
            }
        }
    }
}

// ---------------- K3b (NEW): multi-block rank sort -> d_sort[b][rank] for rank < 512 ----------
__global__ __launch_bounds__(256, 4) void rankK() {
    __shared__ __align__(16) unsigned long long keys[GCAP];
    int b     = blockIdx.x;
    int slice = blockIdx.y;
    int tid   = threadIdx.x;

    int cnt = d_cnt[b]; if (cnt > GCAP) cnt = GCAP;
    const unsigned long long* G = d_gath + b * GCAP;
    for (int i = tid; i < cnt; i += 256) keys[i] = G[i];
    __syncthreads();

    int ps = (cnt + 7) >> 3;                       // elements per slice
    int e0 = slice * ps;
    int e1 = e0 + ps; if (e1 > cnt) e1 = cnt;

    for (int e = e0 + tid; e < e1; e += 256) {
        unsigned long long mine = keys[e];
        int rank = 0;
        int j = 0;
        for (; j + 4 <= cnt; j += 4) {
            rank += (keys[j]     > mine);
            rank += (keys[j + 1] > mine);
            rank += (keys[j + 2] > mine);
            rank += (keys[j + 3] > mine);
        }
        for (; j < cnt; j++) rank += (keys[j] > mine);
        if (rank < KPRE) d_sort[b * KPRE + rank] = mine;
    }
}

// ---------------- K4: decode+clip boxes, mask, Jacobi NMS, write output (no sort) ----------------
__global__ __launch_bounds__(1024, 1) void finalizeK(
    const float* __restrict__ anchors, const float* __restrict__ regs,
    const float* __restrict__ sizes, float* __restrict__ out, int N, int B)
{
    int b = blockIdx.x;
    int tid = threadIdx.x;

    __shared__ __align__(16) unsigned char sm[47296];
    __shared__ int s_changed;
    unsigned int*       maskT = (unsigned int*)sm;            // [512][16]
    float4*             sBox  = (float4*)(sm + 32768);
    float*              sArea = (float*) (sm + 40960);
    float*              sScore= (float*) (sm + 43008);
    int*                sLabel= (int*)   (sm + 45056);
    unsigned int*       keepW = (unsigned int*)(sm + 47104);
    int*                warpCnt = (int*)(sm + 47168);

    int cnt = d_cnt[b]; if (cnt > GCAP) cnt = GCAP;
    int nv  = cnt < KPRE ? cnt : KPRE;
    __syncthreads();
    if (tid == 0) d_cnt[b] = 0;     // reset for next graph replay (after read)

    // decode + clip boxes for top nv (sorted keys from d_sort); default-fill output with -1
    float H = sizes[b * 2 + 0], W = sizes[b * 2 + 1];
    if (tid < nv) {
        unsigned long long v = d_sort[b * KPRE + tid];
        unsigned key = (unsigned)(v >> 32);
        int idx = (int)(~(unsigned)v);
        size_t off = (size_t)b * N + idx;
        float4 a = ((const float4*)anchors)[off];
        float4 r = ((const float4*)regs)[off];
        float w = a.z - a.x, h = a.w - a.y;
        float cx = a.x + 0.5f * w, cy = a.y + 0.5f * h;
        float dx = r.x * 0.1f, dy = r.y * 0.1f, dw = r.z * 0.2f, dh = r.w * 0.2f;
        float pcx = cx + dx * w, pcy = cy + dy * h;
        float pw = expf(dw) * w, ph = expf(dh) * h;
        float x1 = pcx - 0.5f * pw, y1 = pcy - 0.5f * ph;
        float x2 = pcx + 0.5f * pw, y2 = pcy + 0.5f * ph;
        x1 = fminf(fmaxf(x1, 0.f), W); x2 = fminf(fmaxf(x2, 0.f), W);
        y1 = fminf(fmaxf(y1, 0.f), H); y2 = fminf(fmaxf(y2, 0.f), H);
        sBox[tid]  = make_float4(x1, y1, x2, y2);
        sArea[tid] = (x2 - x1) * (y2 - y1);
        sScore[tid]= __uint_as_float(key);
        sLabel[tid]= d_label[off];
    }
    float* outB = out;
    float* outS = out + (size_t)B * MAXDET * 4;
    float* outL = out + (size_t)B * MAXDET * 5;
    if (tid < MAXDET) {
        ((float4*)outB)[b * MAXDET + tid] = make_float4(-1.f, -1.f, -1.f, -1.f);
        outS[b * MAXDET + tid] = -1.f;
        outL[b * MAXDET + tid] = -1.f;
    }
    __syncthreads();

    // ---- TRANSPOSED IoU suppression bitmask, balanced over 1024 threads (R12-proven) ----
    {
        int i    = tid & 511;
        int half = tid >> 9;
        bool v = i < nv;
        float4 bi; float ai = 0.f;
        if (v) { bi = sBox[i]; ai = sArea[i]; }
        int w0 = half * 8;
        int jmax = (i < nv) ? i : nv;          // j < i and j < nv
        #pragma unroll
        for (int ww = 0; ww < 8; ww++) {
            int w = w0 + ww;
            unsigned word = 0;
            if (v) {
                int j0 = w * 32, j1 = j0 + 32;
                if (j1 > jmax) j1 = jmax;
                for (int j = j0; j < j1; j++) {
                    float4 bj = sBox[j];
                    float lx = fmaxf(bi.x, bj.x), ly = fmaxf(bi.y, bj.y);
                    float rx = fminf(bi.z, bj.z), ry = fminf(bi.w, bj.w);
                    float iw = fmaxf(rx - lx, 0.f), ih = fmaxf(ry - ly, 0.f);
                    float inter = iw * ih;
                    float lhs = inter * (1.0f + IOU_THR);
                    float rhs = IOU_THR * (ai + sArea[j] + 1e-9f);
                    if (lhs > rhs) word |= 1u << (j & 31);
                }
            }
            maskT[i * 16 + w] = word;
        }
    }
    // init keep = all valid
    if (tid < 16) {
        int full = nv >> 5, rem = nv & 31;
        keepW[tid] = (tid < full) ? 0xFFFFFFFFu
                   : ((tid == full && rem) ? ((1u << rem) - 1u) : 0u);
    }
    __syncthreads();

    // ---- Jacobi fixpoint iteration: keep[i] = valid[i] && !(exists j<i kept with iou>thr) ----
    for (int it = 0; it < KPRE + 8; it++) {
        unsigned sup = 0;
        if (tid < 512) {
            const uint4* mrow = (const uint4*)(maskT + tid * 16);
            uint4 m0 = mrow[0], m1 = mrow[1], m2 = mrow[2], m3 = mrow[3];
            sup |= (m0.x & keepW[0])  | (m0.y & keepW[1])  | (m0.z & keepW[2])  | (m0.w & keepW[3]);
            sup |= (m1.x & keepW[4])  | (m1.y & keepW[5])  | (m1.z & keepW[6])  | (m1.w & keepW[7]);
            sup |= (m2.x & keepW[8])  | (m2.y & keepW[9])  | (m2.z & keepW[10]) | (m2.w & keepW[11]);
            sup |= (m3.x & keepW[12]) | (m3.y & keepW[13]) | (m3.z & keepW[14]) | (m3.w & keepW[15]);
        }
        bool nb = (tid < nv) && (sup == 0u);
        if (tid == 0) s_changed = 0;
        __syncthreads();
        unsigned wm = __ballot_sync(0xFFFFFFFFu, nb);
        if (tid < 512 && (tid & 31) == 0) {
            int w = tid >> 5;
            if (wm != keepW[w]) { keepW[w] = wm; s_changed = 1; }
        }
        __syncthreads();
        if (!s_changed) break;
    }

    // compact kept candidates (score order) into first <=300 slots
    bool kept = false;
    if (tid < nv) kept = (keepW[tid >> 5] >> (tid & 31)) & 1u;
    unsigned wm = __ballot_sync(0xFFFFFFFFu, kept);
    int w = tid >> 5, lane = tid & 31;
    if (lane == 0) warpCnt[w] = __popc(wm);
    __syncthreads();
    if (kept) {
        int prefix = 0;
        for (int i = 0; i < w; i++) prefix += warpCnt[i];
        int pos = prefix + __popc(wm & ((1u << lane) - 1u));
        if (pos < MAXDET) {
            ((float4*)outB)[b * MAXDET + pos] = sBox[tid];
            outS[b * MAXDET + pos] = sScore[tid];
            outL[b * MAXDET + pos] = (float)sLabel[tid];
        }
    }
}

// ---------------- launch ----------------
extern "C" void kernel_launch(void* const* d_in, const int* in_sizes, int n_in,
                              void* d_out, int out_size) {
    const float* anchors = (const float*)d_in[0];
    const float* regs    = (const float*)d_in[1];
    const float* cls     = (const float*)d_in[2];
    const float* sizes   = (const float*)d_in[3];

    int B = in_sizes[3] / 2;            // sizes is [B,2]
    if (B <= 0 || B > MAXB) B = MAXB;
    int N = in_sizes[0] / (B * 4);      // anchors [B,N,4]
    long long clsElems = (long long)in_sizes[2];
    int C = (int)(clsElems / ((long long)B * N));

    int N4 = (N + 3) / 4;
    int gx = (N4 + 255) / 256;
    dim3 gridV(gx, B);

    if (C == 80) {
        dim3 gridS(((N * 4) + 255) / 256, B);
        scoreK80<<<gridS, 256>>>(cls, N);
    } else {
        dim3 gridBN((N + 255) / 256, B);
        scoreKgen<<<gridBN, 256>>>(cls, N, C);
    }
    selectTK<<<B, 1024>>>();
    gatherK<<<gridV, 256>>>(N, gx);
    rankK<<<dim3(B, 8), 256>>>();
    finalizeK<<<B, 1024>>>(anchors, regs, sizes, (float*)d_out, N, B);
}